// round 9
// baseline (speedup 1.0000x reference)
#include <cuda_runtime.h>
#include <cuda_bf16.h>

#define NB 16384
#define NSTEPS 100
#define DTC 0.01f
#define SQDT 0.1f
#define SIG0 0.5f

typedef unsigned int u32;
typedef unsigned long long u64;

// cvt two f32 -> packed bf16x2 (f0 -> low half, f1 -> high half)
#define CVT2BF(r, f0, f1) \
    asm("cvt.rn.bf16x2.f32 %0, %1, %2;" : "=r"(r) : "f"(f1), "f"(f0))

__device__ __forceinline__ void mma16816(float* d, const u32 a0, const u32 a1,
                                         const u32 a2, const u32 a3,
                                         const u32 b0, const u32 b1) {
    asm volatile(
        "mma.sync.aligned.m16n8k16.row.col.f32.bf16.bf16.f32 "
        "{%0,%1,%2,%3}, {%4,%5,%6,%7}, {%8,%9}, {%0,%1,%2,%3};"
        : "+f"(d[0]), "+f"(d[1]), "+f"(d[2]), "+f"(d[3])
        : "r"(a0), "r"(a1), "r"(a2), "r"(a3), "r"(b0), "r"(b1));
}

__device__ __forceinline__ float sel4(float a, float b, float c, float d, int s) {
    float r = (s == 0) ? a : ((s == 1) ? b : ((s == 2) ? c : d));
    return r;
}

__device__ float g_partials[128];
__device__ unsigned int g_count = 0;

__global__ __launch_bounds__(256) void bsde_mma(
    const float* __restrict__ y0, const float* __restrict__ Y0,
    const float* __restrict__ zW1, const float* __restrict__ zb1,
    const float* __restrict__ zW2, const float* __restrict__ zb2,
    const float* __restrict__ zW3, const float* __restrict__ zb3,
    const float* __restrict__ qW1, const float* __restrict__ qb1,
    const float* __restrict__ qW2, const float* __restrict__ qb2,
    const float* __restrict__ qW3, const float* __restrict__ qb3,
    const float* __restrict__ dW, const float* __restrict__ dZ,
    float* __restrict__ out)
{
    // W2S[m][half][pos]: pos = n*16 + ((kt ^ (n&3))<<2) + tq
    //   u64 = 4 bf16: {W2[16kt+2tq][n], [..+1], [..+8], [..+9]}
    __shared__ u64 W2S[2][2][1024];
    __shared__ float4 W1P[2][64];     // {W1t[n], W1y[n], b1[n], 0}
    __shared__ float4 W3P[2][64];     // z: {w3n0,w3n1,w3n2,0} ; q: {qw3n,0,0,0}
    __shared__ float  B2S[2][64];
    __shared__ float  B3S[2][4];
    __shared__ float4 scratch[2][2][4][32];   // [m][role][pairw][row]
    __shared__ float  ysm[4][32];             // y state published by primary warps
    __shared__ float  red[256];
    __shared__ int    is_last;

    const int tx = threadIdx.x;
    const int l  = tx & 31;
    const int w  = tx >> 5;
    const int pw   = w & 3;      // pair id (SMSP)
    const int role = w >> 2;     // 0 = primary (owns paths/state), 1 = secondary
    const int g  = l >> 2;
    const int tq = l & 3;
    const int ntbase = role * 4; // this warp's nt tile range [ntbase, ntbase+4)

    // ---------------- stage weights ----------------
    for (int idx = tx; idx < 4096; idx += 256) {
        int k = idx >> 6, n = idx & 63;
        int kt = k >> 4, r = k & 15;
        int tt, slot;
        if (r < 8) { tt = r >> 1; slot = r & 1; }
        else       { tt = (r - 8) >> 1; slot = 2 + (r & 1); }
        int pos = n * 16 + ((kt ^ (n & 3)) << 2) + tt;
        {
            float wv = zW2[idx];
            __nv_bfloat16 hi = __float2bfloat16_rn(wv);
            __nv_bfloat16 lo = __float2bfloat16_rn(wv - __bfloat162float(hi));
            ((__nv_bfloat16*)&W2S[0][0][pos])[slot] = hi;
            ((__nv_bfloat16*)&W2S[0][1][pos])[slot] = lo;
        }
        {
            float wv = qW2[idx];
            __nv_bfloat16 hi = __float2bfloat16_rn(wv);
            __nv_bfloat16 lo = __float2bfloat16_rn(wv - __bfloat162float(hi));
            ((__nv_bfloat16*)&W2S[1][0][pos])[slot] = hi;
            ((__nv_bfloat16*)&W2S[1][1][pos])[slot] = lo;
        }
    }
    if (tx < 64) {
        int n = tx;
        W1P[0][n] = make_float4(zW1[n], zW1[64 + n], zb1[n], 0.f);
        W1P[1][n] = make_float4(qW1[n], qW1[64 + n], qb1[n], 0.f);
        W3P[0][n] = make_float4(zW3[n * 3], zW3[n * 3 + 1], zW3[n * 3 + 2], 0.f);
        W3P[1][n] = make_float4(qW3[n], 0.f, 0.f, 0.f);
        B2S[0][n] = zb2[n];
        B2S[1][n] = qb2[n];
    }
    if (tx < 4) {
        B3S[0][tx] = (tx < 3) ? zb3[tx] : 0.f;
        B3S[1][tx] = (tx == 0) ? qb3[0] : 0.f;
    }

    // ---------------- per-path state (primary warps only) ----------------
    const int path = blockIdx.x * 128 + pw * 32 + l;
    float y = y0[0], Yv = Y0[0], t = 0.f, loss = 0.f;
    const float* dWp = dW + path * 3;
    const float* dZp = dZ + path * 3;
    if (role == 0) ysm[pw][l] = y;     // initial publish
    __syncthreads();

    #pragma unroll 1
    for (int i = 0; i < NSTEPS; ++i) {
        float dw0, dw1, dw2, dz0, dz1, dz2;
        if (role == 0) {
            dw0 = dWp[0] * SQDT; dw1 = dWp[1] * SQDT; dw2 = dWp[2] * SQDT;
            dz0 = dZp[0] * SQDT; dz1 = dZp[1] * SQDT; dz2 = dZp[2] * SQDT;
            dWp += NB * 3; dZp += NB * 3;
        }

        // y for the 4 row-slots this lane covers (rows g+8s), from smem
        float ysv[4];
        ysv[0] = ysm[pw][g];
        ysv[1] = ysm[pw][g + 8];
        ysv[2] = ysm[pw][g + 16];
        ysv[3] = ysm[pw][g + 24];

        #pragma unroll 1
        for (int m = 0; m < 2; ++m) {
            // ---- layer 1 in A-fragment layout; bf16 hi/lo split (both warps) ----
            u32 Ahi[4][2][4], Alo[4][2][4];   // [kt][e][s]
            #pragma unroll
            for (int kt = 0; kt < 4; ++kt) {
                #pragma unroll
                for (int e = 0; e < 2; ++e) {
                    int c0 = 16 * kt + 2 * tq + 8 * e;
                    float4 p0 = W1P[m][c0];
                    float4 p1 = W1P[m][c0 + 1];
                    float al0 = fmaf(t, p0.x, p0.z);
                    float al1 = fmaf(t, p1.x, p1.z);
                    #pragma unroll
                    for (int s = 0; s < 4; ++s) {
                        float h0 = fmaxf(fmaf(ysv[s], p0.y, al0), 0.f);
                        float h1 = fmaxf(fmaf(ysv[s], p1.y, al1), 0.f);
                        u32 hp; CVT2BF(hp, h0, h1);
                        float l0 = h0 - __uint_as_float(hp << 16);
                        float l1 = h1 - __uint_as_float(hp & 0xFFFF0000u);
                        u32 lp; CVT2BF(lp, l0, l1);
                        Ahi[kt][e][s] = hp;
                        Alo[kt][e][s] = lp;
                    }
                }
            }

            // ---- GEMM over this warp's 4 nt tiles (kt-outer, persistent acc) ----
            float dacc[4][8];
            #pragma unroll
            for (int ntl = 0; ntl < 4; ++ntl)
                #pragma unroll
                for (int j = 0; j < 8; ++j) dacc[ntl][j] = 0.f;

            const u64* Wh = &W2S[m][0][0];
            const u64* Wl = &W2S[m][1][0];
            const int nb = g;
            const int xk = nb & 3;

            #pragma unroll
            for (int kt = 0; kt < 4; ++kt) {
                #pragma unroll
                for (int ntl = 0; ntl < 4; ++ntl) {
                    int nfull = 8 * (ntbase + ntl) + nb;
                    int pos = nfull * 16 + (((kt ^ xk) & 3) << 2) + tq;
                    u64 bh = Wh[pos];
                    u64 bl = Wl[pos];
                    u32 bh0 = (u32)bh, bh1 = (u32)(bh >> 32);
                    u32 bl0 = (u32)bl, bl1 = (u32)(bl >> 32);
                    float* d0 = &dacc[ntl][0];
                    float* d1 = &dacc[ntl][4];
                    // rows g, g+8
                    mma16816(d0, Ahi[kt][0][0], Ahi[kt][0][1], Ahi[kt][1][0], Ahi[kt][1][1], bh0, bh1);
                    mma16816(d0, Ahi[kt][0][0], Ahi[kt][0][1], Ahi[kt][1][0], Ahi[kt][1][1], bl0, bl1);
                    mma16816(d0, Alo[kt][0][0], Alo[kt][0][1], Alo[kt][1][0], Alo[kt][1][1], bh0, bh1);
                    // rows g+16, g+24
                    mma16816(d1, Ahi[kt][0][2], Ahi[kt][0][3], Ahi[kt][1][2], Ahi[kt][1][3], bh0, bh1);
                    mma16816(d1, Ahi[kt][0][2], Ahi[kt][0][3], Ahi[kt][1][2], Ahi[kt][1][3], bl0, bl1);
                    mma16816(d1, Alo[kt][0][2], Alo[kt][0][3], Alo[kt][1][2], Alo[kt][1][3], bh0, bh1);
                }
            }

            // ---- fused partial epilogue (neurons in own nt tiles are complete) ----
            float o[4][3];
            #pragma unroll
            for (int s = 0; s < 4; ++s) { o[s][0] = 0.f; o[s][1] = 0.f; o[s][2] = 0.f; }

            #pragma unroll
            for (int ntl = 0; ntl < 4; ++ntl) {
                int n0 = 8 * (ntbase + ntl) + 2 * tq;
                float b20 = B2S[m][n0], b21 = B2S[m][n0 + 1];
                float4 w30 = W3P[m][n0];
                float4 w31 = W3P[m][n0 + 1];
                #pragma unroll
                for (int half = 0; half < 2; ++half) {
                    const float* dd = &dacc[ntl][half * 4];
                    #pragma unroll
                    for (int rr = 0; rr < 2; ++rr) {
                        int s = 2 * half + rr;
                        float h0 = fmaxf(dd[2 * rr] + b20, 0.f);
                        float h1 = fmaxf(dd[2 * rr + 1] + b21, 0.f);
                        o[s][0] = fmaf(h0, w30.x, fmaf(h1, w31.x, o[s][0]));
                        o[s][1] = fmaf(h0, w30.y, fmaf(h1, w31.y, o[s][1]));
                        o[s][2] = fmaf(h0, w30.z, fmaf(h1, w31.z, o[s][2]));
                    }
                }
            }

            // quad reduction (lanes with same g hold disjoint col subsets)
            #pragma unroll
            for (int s = 0; s < 4; ++s) {
                #pragma unroll
                for (int j = 0; j < 3; ++j) {
                    float v = o[s][j];
                    v += __shfl_xor_sync(0xffffffffu, v, 1, 32);
                    v += __shfl_xor_sync(0xffffffffu, v, 2, 32);
                    o[s][j] = v;
                }
            }
            float r0 = sel4(o[0][0], o[1][0], o[2][0], o[3][0], tq);
            float r1 = sel4(o[0][1], o[1][1], o[2][1], o[3][1], tq);
            float r2 = sel4(o[0][2], o[1][2], o[2][2], o[3][2], tq);
            scratch[m][role][pw][g + 8 * tq] = make_float4(r0, r1, r2, 0.f);
        }

        __syncthreads();   // partials visible

        if (role == 0) {
            // combine partner halves; this thread's path outputs
            float4 z0 = scratch[0][0][pw][l];
            float4 z1 = scratch[0][1][pw][l];
            float4 q0 = scratch[1][0][pw][l];
            float4 q1 = scratch[1][1][pw][l];
            float o0 = z0.x + z1.x + B3S[0][0];
            float o1 = z0.y + z1.y + B3S[0][1];
            float o2 = z0.z + z1.z + B3S[0][2];
            float qv = q0.x + q1.x + B3S[1][0];

            // SDE / BSDE update (residual = z.dw - z.dz; Y cancels)
            float zdw = o0 * dw0 + o1 * dw1 + o2 * dw2;
            float zdz = o0 * dz0 + o1 * dz1 + o2 * dz2;
            float f = 0.5f * qv * qv;
            y  = y + qv * DTC + SIG0 * (dw0 + dw1 + dw2);
            Yv = Yv - f * DTC + zdw;
            float r = zdw - zdz;
            loss = fmaf(r, r, loss);
            ysm[pw][l] = y;            // publish for next step
        }
        t += DTC;
        __syncthreads();   // y visible before next step's reads
    }

    if (role == 0) {
        float term = Yv - y * y;
        loss = fmaf(term, term, loss);
    } else {
        loss = 0.f;
    }

    // ---------------- reduction ----------------
    red[tx] = loss;
    __syncthreads();
    #pragma unroll
    for (int s = 128; s > 0; s >>= 1) {
        if (tx < s) red[tx] += red[tx + s];
        __syncthreads();
    }
    if (tx == 0) {
        g_partials[blockIdx.x] = red[0];
        __threadfence();
        unsigned int prev = atomicAdd(&g_count, 1u);
        is_last = (prev == gridDim.x - 1) ? 1 : 0;
    }
    __syncthreads();
    if (is_last) {
        __threadfence();
        red[tx] = (tx < 128) ? g_partials[tx] : 0.f;
        __syncthreads();
        #pragma unroll
        for (int s = 128; s > 0; s >>= 1) {
            if (tx < s) red[tx] += red[tx + s];
            __syncthreads();
        }
        if (tx == 0) {
            out[0] = red[0] * (1.0f / (float)NB);
            g_count = 0;               // reset for graph replay
        }
    }
}

extern "C" void kernel_launch(void* const* d_in, const int* in_sizes, int n_in,
                              void* d_out, int out_size)
{
    const float* y0  = (const float*)d_in[0];
    const float* Y0  = (const float*)d_in[1];
    const float* zW1 = (const float*)d_in[2];
    const float* zb1 = (const float*)d_in[3];
    const float* zW2 = (const float*)d_in[4];
    const float* zb2 = (const float*)d_in[5];
    const float* zW3 = (const float*)d_in[6];
    const float* zb3 = (const float*)d_in[7];
    const float* qW1 = (const float*)d_in[8];
    const float* qb1 = (const float*)d_in[9];
    const float* qW2 = (const float*)d_in[10];
    const float* qb2 = (const float*)d_in[11];
    const float* qW3 = (const float*)d_in[12];
    const float* qb3 = (const float*)d_in[13];
    const float* dW  = (const float*)d_in[14];
    const float* dZ  = (const float*)d_in[15];

    bsde_mma<<<128, 256>>>(y0, Y0, zW1, zb1, zW2, zb2, zW3, zb3,
                           qW1, qb1, qW2, qb2, qW3, qb3, dW, dZ,
                           (float*)d_out);
}

// round 10
// speedup vs baseline: 1.1498x; 1.1498x over previous
#include <cuda_runtime.h>
#include <cuda_bf16.h>

#define NB 16384
#define NSTEPS 100
#define DTC 0.01f
#define SQDT 0.1f
#define SIG0 0.5f

typedef unsigned int u32;
typedef unsigned long long u64;

// cvt two f32 -> packed bf16x2 (f0 -> low half, f1 -> high half)
#define CVT2BF(r, f0, f1) \
    asm("cvt.rn.bf16x2.f32 %0, %1, %2;" : "=r"(r) : "f"(f1), "f"(f0))

__device__ __forceinline__ void mma16816(float* d, const u32 a0, const u32 a1,
                                         const u32 a2, const u32 a3,
                                         const u32 b0, const u32 b1) {
    asm volatile(
        "mma.sync.aligned.m16n8k16.row.col.f32.bf16.bf16.f32 "
        "{%0,%1,%2,%3}, {%4,%5,%6,%7}, {%8,%9}, {%0,%1,%2,%3};"
        : "+f"(d[0]), "+f"(d[1]), "+f"(d[2]), "+f"(d[3])
        : "r"(a0), "r"(a1), "r"(a2), "r"(a3), "r"(b0), "r"(b1));
}

__device__ float g_partials[128];
__device__ unsigned int g_count = 0;

__global__ __launch_bounds__(256) void bsde_mma(
    const float* __restrict__ y0, const float* __restrict__ Y0,
    const float* __restrict__ zW1, const float* __restrict__ zb1,
    const float* __restrict__ zW2, const float* __restrict__ zb2,
    const float* __restrict__ zW3, const float* __restrict__ zb3,
    const float* __restrict__ qW1, const float* __restrict__ qb1,
    const float* __restrict__ qW2, const float* __restrict__ qb2,
    const float* __restrict__ qW3, const float* __restrict__ qb3,
    const float* __restrict__ dW, const float* __restrict__ dZ,
    float* __restrict__ out)
{
    // W2S[m][half][pos]: pos = n*16 + ((kt ^ (n&3))<<2) + tq
    //   u64 = 4 bf16: {W2[16kt+2tq][n], [..+1], [..+8], [..+9]}
    __shared__ u64 W2S[2][2][1024];
    __shared__ float4 W1P[2][64];     // {W1t[n], W1y[n], b1[n], 0}
    __shared__ float4 W3P[2][64];     // z: {w3n0,w3n1,w3n2,0} ; q: {qw3n,0,0,0}
    __shared__ float  B2S[2][64];
    __shared__ float  B3S[2][4];
    __shared__ float  red[256];
    __shared__ int    is_last;

    const int tx = threadIdx.x;
    const int l  = tx & 31;
    const int w  = tx >> 5;          // 8 warps, each owns 16 paths
    const int g  = l >> 2;
    const int tq = l & 3;

    // ---------------- stage weights ----------------
    for (int idx = tx; idx < 4096; idx += 256) {
        int k = idx >> 6, n = idx & 63;
        int kt = k >> 4, r = k & 15;
        int tt, slot;
        if (r < 8) { tt = r >> 1; slot = r & 1; }
        else       { tt = (r - 8) >> 1; slot = 2 + (r & 1); }
        int pos = n * 16 + ((kt ^ (n & 3)) << 2) + tt;
        {
            float wv = zW2[idx];
            __nv_bfloat16 hi = __float2bfloat16_rn(wv);
            __nv_bfloat16 lo = __float2bfloat16_rn(wv - __bfloat162float(hi));
            ((__nv_bfloat16*)&W2S[0][0][pos])[slot] = hi;
            ((__nv_bfloat16*)&W2S[0][1][pos])[slot] = lo;
        }
        {
            float wv = qW2[idx];
            __nv_bfloat16 hi = __float2bfloat16_rn(wv);
            __nv_bfloat16 lo = __float2bfloat16_rn(wv - __bfloat162float(hi));
            ((__nv_bfloat16*)&W2S[1][0][pos])[slot] = hi;
            ((__nv_bfloat16*)&W2S[1][1][pos])[slot] = lo;
        }
    }
    if (tx < 64) {
        int n = tx;
        W1P[0][n] = make_float4(zW1[n], zW1[64 + n], zb1[n], 0.f);
        W1P[1][n] = make_float4(qW1[n], qW1[64 + n], qb1[n], 0.f);
        W3P[0][n] = make_float4(zW3[n * 3], zW3[n * 3 + 1], zW3[n * 3 + 2], 0.f);
        W3P[1][n] = make_float4(qW3[n], 0.f, 0.f, 0.f);
        B2S[0][n] = zb2[n];
        B2S[1][n] = qb2[n];
    }
    if (tx < 4) {
        B3S[0][tx] = (tx < 3) ? zb3[tx] : 0.f;
        B3S[1][tx] = (tx == 0) ? qb3[0] : 0.f;
    }
    __syncthreads();

    // ---------------- per-path state: lane l < 16 owns path base + l ----------------
    const int path = blockIdx.x * 128 + w * 16 + (l & 15);
    const bool owner = (l < 16);
    float y = y0[0], Yv = Y0[0], t = 0.f, loss = 0.f;
    const float* dWp = dW + path * 3;
    const float* dZp = dZ + path * 3;

    #pragma unroll 1
    for (int i = 0; i < NSTEPS; ++i) {
        float dw0 = 0.f, dw1 = 0.f, dw2 = 0.f, dz0 = 0.f, dz1 = 0.f, dz2 = 0.f;
        if (owner) {
            dw0 = dWp[0] * SQDT; dw1 = dWp[1] * SQDT; dw2 = dWp[2] * SQDT;
            dz0 = dZp[0] * SQDT; dz1 = dZp[1] * SQDT; dz2 = dZp[2] * SQDT;
        }
        dWp += NB * 3; dZp += NB * 3;

        // y for the 2 rows this lane covers in the 16-row tile
        float yg  = __shfl_sync(0xffffffffu, y, g, 32);
        float yg8 = __shfl_sync(0xffffffffu, y, g + 8, 32);

        float zo0 = 0.f, zo1 = 0.f, zo2 = 0.f, qvv = 0.f;

        #pragma unroll 1
        for (int m = 0; m < 2; ++m) {
            // ---- layer 1 in m16n8k16 A-fragment layout; bf16 hi/lo split ----
            // Ahi[kt][e][s]: e=0 -> cols 16kt+2tq(+1), e=1 -> cols +8; s=0 row g, s=1 row g+8
            u32 Ahi[4][2][2], Alo[4][2][2];
            #pragma unroll
            for (int kt = 0; kt < 4; ++kt) {
                #pragma unroll
                for (int e = 0; e < 2; ++e) {
                    int c0 = 16 * kt + 2 * tq + 8 * e;
                    float4 p0 = W1P[m][c0];
                    float4 p1 = W1P[m][c0 + 1];
                    float al0 = fmaf(t, p0.x, p0.z);
                    float al1 = fmaf(t, p1.x, p1.z);
                    float hg0 = fmaxf(fmaf(yg,  p0.y, al0), 0.f);
                    float hg1 = fmaxf(fmaf(yg,  p1.y, al1), 0.f);
                    float h80 = fmaxf(fmaf(yg8, p0.y, al0), 0.f);
                    float h81 = fmaxf(fmaf(yg8, p1.y, al1), 0.f);
                    u32 hp, lp;
                    CVT2BF(hp, hg0, hg1);
                    CVT2BF(lp, hg0 - __uint_as_float(hp << 16),
                               hg1 - __uint_as_float(hp & 0xFFFF0000u));
                    Ahi[kt][e][0] = hp;  Alo[kt][e][0] = lp;
                    CVT2BF(hp, h80, h81);
                    CVT2BF(lp, h80 - __uint_as_float(hp << 16),
                               h81 - __uint_as_float(hp & 0xFFFF0000u));
                    Ahi[kt][e][1] = hp;  Alo[kt][e][1] = lp;
                }
            }

            // ---- GEMM: kt-outer, 8 persistent nt accumulators ----
            float dacc[8][4];
            #pragma unroll
            for (int nt = 0; nt < 8; ++nt)
                #pragma unroll
                for (int j = 0; j < 4; ++j) dacc[nt][j] = 0.f;

            const u64* Wh = &W2S[m][0][0];
            const u64* Wl = &W2S[m][1][0];
            const int xk = g & 3;

            #pragma unroll
            for (int kt = 0; kt < 4; ++kt) {
                const int kperm = ((kt ^ xk) & 3) << 2;
                #pragma unroll
                for (int nt = 0; nt < 8; ++nt) {
                    int pos = (8 * nt + g) * 16 + kperm + tq;
                    u64 bh = Wh[pos];
                    u64 bl = Wl[pos];
                    u32 bh0 = (u32)bh, bh1 = (u32)(bh >> 32);
                    u32 bl0 = (u32)bl, bl1 = (u32)(bl >> 32);
                    float* d = dacc[nt];
                    mma16816(d, Ahi[kt][0][0], Ahi[kt][0][1], Ahi[kt][1][0], Ahi[kt][1][1], bh0, bh1);
                    mma16816(d, Ahi[kt][0][0], Ahi[kt][0][1], Ahi[kt][1][0], Ahi[kt][1][1], bl0, bl1);
                    mma16816(d, Alo[kt][0][0], Alo[kt][0][1], Alo[kt][1][0], Alo[kt][1][1], bh0, bh1);
                }
            }

            // ---- fused epilogue: relu(+b2) then layer-3 into per-row sums ----
            // D mapping: d[0]=D[g][n0], d[1]=D[g][n0+1], d[2]=D[g+8][n0], d[3]=D[g+8][n0+1]
            float og[3]  = {0.f, 0.f, 0.f};
            float og8[3] = {0.f, 0.f, 0.f};
            #pragma unroll
            for (int nt = 0; nt < 8; ++nt) {
                int n0 = 8 * nt + 2 * tq;
                float b20 = B2S[m][n0], b21 = B2S[m][n0 + 1];
                float4 w30 = W3P[m][n0];
                float4 w31 = W3P[m][n0 + 1];
                const float* d = dacc[nt];
                float h0 = fmaxf(d[0] + b20, 0.f);
                float h1 = fmaxf(d[1] + b21, 0.f);
                og[0] = fmaf(h0, w30.x, fmaf(h1, w31.x, og[0]));
                og[1] = fmaf(h0, w30.y, fmaf(h1, w31.y, og[1]));
                og[2] = fmaf(h0, w30.z, fmaf(h1, w31.z, og[2]));
                float h2 = fmaxf(d[2] + b20, 0.f);
                float h3 = fmaxf(d[3] + b21, 0.f);
                og8[0] = fmaf(h2, w30.x, fmaf(h3, w31.x, og8[0]));
                og8[1] = fmaf(h2, w30.y, fmaf(h3, w31.y, og8[1]));
                og8[2] = fmaf(h2, w30.z, fmaf(h3, w31.z, og8[2]));
            }

            // quad reduction over tq (cols), then redistribute rows -> path lanes
            const int srcl = (l & 7) * 4;
            #pragma unroll
            for (int j = 0; j < 3; ++j) {
                float v = og[j];
                v += __shfl_xor_sync(0xffffffffu, v, 1, 32);
                v += __shfl_xor_sync(0xffffffffu, v, 2, 32);
                float v8 = og8[j];
                v8 += __shfl_xor_sync(0xffffffffu, v8, 1, 32);
                v8 += __shfl_xor_sync(0xffffffffu, v8, 2, 32);
                // lane p wants row p: p<8 -> v at lane 4p ; p>=8 -> v8 at lane 4(p-8)
                float a = __shfl_sync(0xffffffffu, v, srcl, 32);
                float b = __shfl_sync(0xffffffffu, v8, srcl, 32);
                float val = (l & 8) ? b : a;
                if (m == 0) {
                    if (j == 0) zo0 = val + B3S[0][0];
                    else if (j == 1) zo1 = val + B3S[0][1];
                    else zo2 = val + B3S[0][2];
                } else {
                    if (j == 0) qvv = val + B3S[1][0];
                }
            }
        }

        // ---- SDE / BSDE update (residual = z.dw - z.dz; Y cancels) ----
        if (owner) {
            float zdw = zo0 * dw0 + zo1 * dw1 + zo2 * dw2;
            float zdz = zo0 * dz0 + zo1 * dz1 + zo2 * dz2;
            float f = 0.5f * qvv * qvv;
            y  = y + qvv * DTC + SIG0 * (dw0 + dw1 + dw2);
            Yv = Yv - f * DTC + zdw;
            float r = zdw - zdz;
            loss = fmaf(r, r, loss);
        }
        t += DTC;
    }
    if (owner) {
        float term = Yv - y * y;
        loss = fmaf(term, term, loss);
    } else {
        loss = 0.f;
    }

    // ---------------- reduction ----------------
    red[tx] = loss;
    __syncthreads();
    #pragma unroll
    for (int s = 128; s > 0; s >>= 1) {
        if (tx < s) red[tx] += red[tx + s];
        __syncthreads();
    }
    if (tx == 0) {
        g_partials[blockIdx.x] = red[0];
        __threadfence();
        unsigned int prev = atomicAdd(&g_count, 1u);
        is_last = (prev == gridDim.x - 1) ? 1 : 0;
    }
    __syncthreads();
    if (is_last) {
        __threadfence();
        red[tx] = (tx < 128) ? g_partials[tx] : 0.f;
        __syncthreads();
        #pragma unroll
        for (int s = 128; s > 0; s >>= 1) {
            if (tx < s) red[tx] += red[tx + s];
            __syncthreads();
        }
        if (tx == 0) {
            out[0] = red[0] * (1.0f / (float)NB);
            g_count = 0;               // reset for graph replay
        }
    }
}

extern "C" void kernel_launch(void* const* d_in, const int* in_sizes, int n_in,
                              void* d_out, int out_size)
{
    const float* y0  = (const float*)d_in[0];
    const float* Y0  = (const float*)d_in[1];
    const float* zW1 = (const float*)d_in[2];
    const float* zb1 = (const float*)d_in[3];
    const float* zW2 = (const float*)d_in[4];
    const float* zb2 = (const float*)d_in[5];
    const float* zW3 = (const float*)d_in[6];
    const float* zb3 = (const float*)d_in[7];
    const float* qW1 = (const float*)d_in[8];
    const float* qb1 = (const float*)d_in[9];
    const float* qW2 = (const float*)d_in[10];
    const float* qb2 = (const float*)d_in[11];
    const float* qW3 = (const float*)d_in[12];
    const float* qb3 = (const float*)d_in[13];
    const float* dW  = (const float*)d_in[14];
    const float* dZ  = (const float*)d_in[15];

    bsde_mma<<<128, 256>>>(y0, Y0, zW1, zb1, zW2, zb2, zW3, zb3,
                           qW1, qb1, qW2, qb2, qW3, qb3, dW, dZ,
                           (float*)d_out);
}

// round 11
// speedup vs baseline: 1.4199x; 1.2350x over previous
#include <cuda_runtime.h>
#include <cuda_fp16.h>

#define NB 16384
#define NSTEPS 100
#define DTC 0.01f
#define SQDT 0.1f
#define SIG0 0.5f

typedef unsigned int u32;
typedef unsigned long long u64;

__device__ __forceinline__ u32 h2u(__half2 h) {
    u32 r; *(__half2*)&r = h; return r;
}

__device__ __forceinline__ void mma16816(float* d, const u32 a0, const u32 a1,
                                         const u32 a2, const u32 a3,
                                         const u32 b0, const u32 b1) {
    asm volatile(
        "mma.sync.aligned.m16n8k16.row.col.f32.f16.f16.f32 "
        "{%0,%1,%2,%3}, {%4,%5,%6,%7}, {%8,%9}, {%0,%1,%2,%3};"
        : "+f"(d[0]), "+f"(d[1]), "+f"(d[2]), "+f"(d[3])
        : "r"(a0), "r"(a1), "r"(a2), "r"(a3), "r"(b0), "r"(b1));
}

__device__ float g_partials[128];
__device__ unsigned int g_count = 0;

__global__ __launch_bounds__(256) void bsde_mma(
    const float* __restrict__ y0, const float* __restrict__ Y0,
    const float* __restrict__ zW1, const float* __restrict__ zb1,
    const float* __restrict__ zW2, const float* __restrict__ zb2,
    const float* __restrict__ zW3, const float* __restrict__ zb3,
    const float* __restrict__ qW1, const float* __restrict__ qb1,
    const float* __restrict__ qW2, const float* __restrict__ qb2,
    const float* __restrict__ qW3, const float* __restrict__ qb3,
    const float* __restrict__ dW, const float* __restrict__ dZ,
    float* __restrict__ out)
{
    // W2S[m][pos]: pos = n*16 + ((kt ^ (n&3))<<2) + tq
    //   u64 = 4 fp16: {W2[16kt+2tq][n], [..+1], [..+8], [..+9]}
    __shared__ u64 W2S[2][1024];
    __shared__ float4 W1P[2][64];     // {W1t[n], W1y[n], b1[n], 0}
    __shared__ float4 W3P[2][64];     // z: {w3n0,w3n1,w3n2,b2n} ; q: {qw3n,0,0,b2n}
    __shared__ float  B3S[2][4];
    __shared__ float  red[256];
    __shared__ int    is_last;

    const int tx = threadIdx.x;
    const int l  = tx & 31;
    const int w  = tx >> 5;          // 8 warps, each owns 16 paths
    const int g  = l >> 2;
    const int tq = l & 3;

    // ---------------- stage weights ----------------
    for (int idx = tx; idx < 4096; idx += 256) {
        int k = idx >> 6, n = idx & 63;
        int kt = k >> 4, r = k & 15;
        int tt, slot;
        if (r < 8) { tt = r >> 1; slot = r & 1; }
        else       { tt = (r - 8) >> 1; slot = 2 + (r & 1); }
        int pos = n * 16 + ((kt ^ (n & 3)) << 2) + tt;
        ((__half*)&W2S[0][pos])[slot] = __float2half_rn(zW2[idx]);
        ((__half*)&W2S[1][pos])[slot] = __float2half_rn(qW2[idx]);
    }
    if (tx < 64) {
        int n = tx;
        W1P[0][n] = make_float4(zW1[n], zW1[64 + n], zb1[n], 0.f);
        W1P[1][n] = make_float4(qW1[n], qW1[64 + n], qb1[n], 0.f);
        W3P[0][n] = make_float4(zW3[n * 3], zW3[n * 3 + 1], zW3[n * 3 + 2], zb2[n]);
        W3P[1][n] = make_float4(qW3[n], 0.f, 0.f, qb2[n]);
    }
    if (tx < 4) {
        B3S[0][tx] = (tx < 3) ? zb3[tx] : 0.f;
        B3S[1][tx] = (tx == 0) ? qb3[0] : 0.f;
    }
    __syncthreads();

    // ---------------- per-path state: lane l < 16 owns path base + l ----------------
    const int path = blockIdx.x * 128 + w * 16 + (l & 15);
    const bool owner = (l < 16);
    float y = y0[0], Yv = Y0[0], t = 0.f, loss = 0.f;
    const float* dWp = dW + path * 3;
    const float* dZp = dZ + path * 3;

    #pragma unroll 1
    for (int i = 0; i < NSTEPS; ++i) {
        float dw0 = 0.f, dw1 = 0.f, dw2 = 0.f, dz0 = 0.f, dz1 = 0.f, dz2 = 0.f;
        if (owner) {
            dw0 = dWp[0] * SQDT; dw1 = dWp[1] * SQDT; dw2 = dWp[2] * SQDT;
            dz0 = dZp[0] * SQDT; dz1 = dZp[1] * SQDT; dz2 = dZp[2] * SQDT;
        }
        dWp += NB * 3; dZp += NB * 3;

        // y for the 2 rows this lane covers in the 16-row tile
        float yg  = __shfl_sync(0xffffffffu, y, g, 32);
        float yg8 = __shfl_sync(0xffffffffu, y, g + 8, 32);

        float zo0 = 0.f, zo1 = 0.f, zo2 = 0.f, qvv = 0.f;

        #pragma unroll 1
        for (int m = 0; m < 2; ++m) {
            // ---- layer 1 in m16n8k16 A-fragment layout; fp16 hi/lo split of A ----
            // Ahi[kt][e][s]: e=0 -> cols 16kt+2tq(+1), e=1 -> +8; s=0 row g, s=1 row g+8
            u32 Ahi[4][2][2], Alo[4][2][2];
            #pragma unroll
            for (int kt = 0; kt < 4; ++kt) {
                #pragma unroll
                for (int e = 0; e < 2; ++e) {
                    int c0 = 16 * kt + 2 * tq + 8 * e;
                    float4 p0 = W1P[m][c0];
                    float4 p1 = W1P[m][c0 + 1];
                    float al0 = fmaf(t, p0.x, p0.z);
                    float al1 = fmaf(t, p1.x, p1.z);
                    float hg0 = fmaxf(fmaf(yg,  p0.y, al0), 0.f);
                    float hg1 = fmaxf(fmaf(yg,  p1.y, al1), 0.f);
                    float h80 = fmaxf(fmaf(yg8, p0.y, al0), 0.f);
                    float h81 = fmaxf(fmaf(yg8, p1.y, al1), 0.f);
                    __half2 hp0 = __floats2half2_rn(hg0, hg1);
                    float2 fb0 = __half22float2(hp0);
                    Ahi[kt][e][0] = h2u(hp0);
                    Alo[kt][e][0] = h2u(__floats2half2_rn(hg0 - fb0.x, hg1 - fb0.y));
                    __half2 hp1 = __floats2half2_rn(h80, h81);
                    float2 fb1 = __half22float2(hp1);
                    Ahi[kt][e][1] = h2u(hp1);
                    Alo[kt][e][1] = h2u(__floats2half2_rn(h80 - fb1.x, h81 - fb1.y));
                }
            }

            // ---- GEMM: kt-outer, 8 persistent nt accumulators, 2 MMAs/pos ----
            float dacc[8][4];
            #pragma unroll
            for (int nt = 0; nt < 8; ++nt)
                #pragma unroll
                for (int j = 0; j < 4; ++j) dacc[nt][j] = 0.f;

            const u64* Wh = &W2S[m][0];
            const int xk = g & 3;

            #pragma unroll
            for (int kt = 0; kt < 4; ++kt) {
                const int kperm = ((kt ^ xk) & 3) << 2;
                #pragma unroll
                for (int nt = 0; nt < 8; ++nt) {
                    int pos = (8 * nt + g) * 16 + kperm + tq;
                    u64 bh = Wh[pos];
                    u32 bh0 = (u32)bh, bh1 = (u32)(bh >> 32);
                    float* d = dacc[nt];
                    mma16816(d, Ahi[kt][0][0], Ahi[kt][0][1], Ahi[kt][1][0], Ahi[kt][1][1], bh0, bh1);
                    mma16816(d, Alo[kt][0][0], Alo[kt][0][1], Alo[kt][1][0], Alo[kt][1][1], bh0, bh1);
                }
            }

            // ---- fused epilogue: relu(+b2 in w3.w) then layer-3 per-row sums ----
            // D mapping: d[0]=D[g][n0], d[1]=D[g][n0+1], d[2]=D[g+8][n0], d[3]=D[g+8][n0+1]
            float og[3]  = {0.f, 0.f, 0.f};
            float og8[3] = {0.f, 0.f, 0.f};
            #pragma unroll
            for (int nt = 0; nt < 8; ++nt) {
                int n0 = 8 * nt + 2 * tq;
                float4 w30 = W3P[m][n0];
                float4 w31 = W3P[m][n0 + 1];
                const float* d = dacc[nt];
                float h0 = fmaxf(d[0] + w30.w, 0.f);
                float h1 = fmaxf(d[1] + w31.w, 0.f);
                og[0] = fmaf(h0, w30.x, fmaf(h1, w31.x, og[0]));
                og[1] = fmaf(h0, w30.y, fmaf(h1, w31.y, og[1]));
                og[2] = fmaf(h0, w30.z, fmaf(h1, w31.z, og[2]));
                float h2v = fmaxf(d[2] + w30.w, 0.f);
                float h3 = fmaxf(d[3] + w31.w, 0.f);
                og8[0] = fmaf(h2v, w30.x, fmaf(h3, w31.x, og8[0]));
                og8[1] = fmaf(h2v, w30.y, fmaf(h3, w31.y, og8[1]));
                og8[2] = fmaf(h2v, w30.z, fmaf(h3, w31.z, og8[2]));
            }

            // quad reduction over tq (cols), then redistribute rows -> path lanes
            const int srcl = (l & 7) * 4;
            #pragma unroll
            for (int j = 0; j < 3; ++j) {
                float v = og[j];
                v += __shfl_xor_sync(0xffffffffu, v, 1, 32);
                v += __shfl_xor_sync(0xffffffffu, v, 2, 32);
                float v8 = og8[j];
                v8 += __shfl_xor_sync(0xffffffffu, v8, 1, 32);
                v8 += __shfl_xor_sync(0xffffffffu, v8, 2, 32);
                // lane p wants row p: p<8 -> v at lane 4p ; p>=8 -> v8 at lane 4(p-8)
                float a = __shfl_sync(0xffffffffu, v, srcl, 32);
                float b = __shfl_sync(0xffffffffu, v8, srcl, 32);
                float val = (l & 8) ? b : a;
                if (m == 0) {
                    if (j == 0) zo0 = val + B3S[0][0];
                    else if (j == 1) zo1 = val + B3S[0][1];
                    else zo2 = val + B3S[0][2];
                } else {
                    if (j == 0) qvv = val + B3S[1][0];
                }
            }
        }

        // ---- SDE / BSDE update (residual = z.dw - z.dz; Y cancels) ----
        if (owner) {
            float zdw = zo0 * dw0 + zo1 * dw1 + zo2 * dw2;
            float zdz = zo0 * dz0 + zo1 * dz1 + zo2 * dz2;
            float f = 0.5f * qvv * qvv;
            y  = y + qvv * DTC + SIG0 * (dw0 + dw1 + dw2);
            Yv = Yv - f * DTC + zdw;
            float r = zdw - zdz;
            loss = fmaf(r, r, loss);
        }
        t += DTC;
    }
    if (owner) {
        float term = Yv - y * y;
        loss = fmaf(term, term, loss);
    } else {
        loss = 0.f;
    }

    // ---------------- reduction ----------------
    red[tx] = loss;
    __syncthreads();
    #pragma unroll
    for (int s = 128; s > 0; s >>= 1) {
        if (tx < s) red[tx] += red[tx + s];
        __syncthreads();
    }
    if (tx == 0) {
        g_partials[blockIdx.x] = red[0];
        __threadfence();
        unsigned int prev = atomicAdd(&g_count, 1u);
        is_last = (prev == gridDim.x - 1) ? 1 : 0;
    }
    __syncthreads();
    if (is_last) {
        __threadfence();
        red[tx] = (tx < 128) ? g_partials[tx] : 0.f;
        __syncthreads();
        #pragma unroll
        for (int s = 128; s > 0; s >>= 1) {
            if (tx < s) red[tx] += red[tx + s];
            __syncthreads();
        }
        if (tx == 0) {
            out[0] = red[0] * (1.0f / (float)NB);
            g_count = 0;               // reset for graph replay
        }
    }
}

extern "C" void kernel_launch(void* const* d_in, const int* in_sizes, int n_in,
                              void* d_out, int out_size)
{
    const float* y0  = (const float*)d_in[0];
    const float* Y0  = (const float*)d_in[1];
    const float* zW1 = (const float*)d_in[2];
    const float* zb1 = (const float*)d_in[3];
    const float* zW2 = (const float*)d_in[4];
    const float* zb2 = (const float*)d_in[5];
    const float* zW3 = (const float*)d_in[6];
    const float* zb3 = (const float*)d_in[7];
    const float* qW1 = (const float*)d_in[8];
    const float* qb1 = (const float*)d_in[9];
    const float* qW2 = (const float*)d_in[10];
    const float* qb2 = (const float*)d_in[11];
    const float* qW3 = (const float*)d_in[12];
    const float* qb3 = (const float*)d_in[13];
    const float* dW  = (const float*)d_in[14];
    const float* dZ  = (const float*)d_in[15];

    bsde_mma<<<128, 256>>>(y0, Y0, zW1, zb1, zW2, zb2, zW3, zb3,
                           qW1, qb1, qW2, qb2, qW3, qb3, dW, dZ,
                           (float*)d_out);
}

// round 12
// speedup vs baseline: 2.4107x; 1.6978x over previous
#include <cuda_runtime.h>
#include <cuda_fp16.h>

#define NB 16384
#define NSTEPS 100
#define DTC 0.01f
#define SQDT 0.1f
#define SIG0 0.5f

typedef unsigned int u32;
typedef unsigned long long u64;

__device__ __forceinline__ u32 h2u(__half2 h) {
    u32 r; *(__half2*)&r = h; return r;
}

__device__ __forceinline__ void mma16816(float* d, const u32 a0, const u32 a1,
                                         const u32 a2, const u32 a3,
                                         const u32 b0, const u32 b1) {
    asm volatile(
        "mma.sync.aligned.m16n8k16.row.col.f32.f16.f16.f32 "
        "{%0,%1,%2,%3}, {%4,%5,%6,%7}, {%8,%9}, {%0,%1,%2,%3};"
        : "+f"(d[0]), "+f"(d[1]), "+f"(d[2]), "+f"(d[3])
        : "r"(a0), "r"(a1), "r"(a2), "r"(a3), "r"(b0), "r"(b1));
}

__device__ float g_partials[128];
__device__ unsigned int g_count = 0;

__global__ __launch_bounds__(256) void bsde_mma(
    const float* __restrict__ y0, const float* __restrict__ Y0,
    const float* __restrict__ zW1, const float* __restrict__ zb1,
    const float* __restrict__ zW2, const float* __restrict__ zb2,
    const float* __restrict__ zW3, const float* __restrict__ zb3,
    const float* __restrict__ qW1, const float* __restrict__ qb1,
    const float* __restrict__ qW2, const float* __restrict__ qb2,
    const float* __restrict__ qW3, const float* __restrict__ qb3,
    const float* __restrict__ dW, const float* __restrict__ dZ,
    float* __restrict__ out)
{
    // Staging only (read once into registers): pos = n*16 + kt*4 + tq
    //   u64 = 4 fp16: {W2[16kt+2tq][n], [..+1], [..+8], [..+9]}
    __shared__ u64 W2S[2][1024];
    __shared__ float4 W1P[2][64];     // {W1t[n], W1y[n], b1[n], 0}
    __shared__ float4 W3P[2][64];     // z: {w3n0,w3n1,w3n2,b2n} ; q: {qw3n,0,0,b2n}
    __shared__ float  B3S[2][4];
    __shared__ float  red[256];
    __shared__ int    is_last;

    const int tx = threadIdx.x;
    const int l  = tx & 31;
    const int w  = tx >> 5;          // 8 warps, each owns 16 paths
    const int g  = l >> 2;
    const int tq = l & 3;

    // ---------------- stage weights ----------------
    for (int idx = tx; idx < 4096; idx += 256) {
        int k = idx >> 6, n = idx & 63;
        int kt = k >> 4, r = k & 15;
        int tt, slot;
        if (r < 8) { tt = r >> 1; slot = r & 1; }
        else       { tt = (r - 8) >> 1; slot = 2 + (r & 1); }
        int pos = n * 16 + kt * 4 + tt;
        ((__half*)&W2S[0][pos])[slot] = __float2half_rn(zW2[idx]);
        ((__half*)&W2S[1][pos])[slot] = __float2half_rn(qW2[idx]);
    }
    if (tx < 64) {
        int n = tx;
        W1P[0][n] = make_float4(zW1[n], zW1[64 + n], zb1[n], 0.f);
        W1P[1][n] = make_float4(qW1[n], qW1[64 + n], qb1[n], 0.f);
        W3P[0][n] = make_float4(zW3[n * 3], zW3[n * 3 + 1], zW3[n * 3 + 2], zb2[n]);
        W3P[1][n] = make_float4(qW3[n], 0.f, 0.f, qb2[n]);
    }
    if (tx < 4) {
        B3S[0][tx] = (tx < 3) ? zb3[tx] : 0.f;
        B3S[1][tx] = (tx == 0) ? qb3[0] : 0.f;
    }
    __syncthreads();

    // ---------------- hoist B fragments into registers (once) ----------------
    u32 Bl[2][4][8], Bh[2][4][8];
    #pragma unroll
    for (int m = 0; m < 2; ++m)
        #pragma unroll
        for (int kt = 0; kt < 4; ++kt)
            #pragma unroll
            for (int nt = 0; nt < 8; ++nt) {
                u64 b = W2S[m][(8 * nt + g) * 16 + kt * 4 + tq];
                Bl[m][kt][nt] = (u32)b;
                Bh[m][kt][nt] = (u32)(b >> 32);
            }

    // ---------------- per-path state: lane l < 16 owns path base + l ----------------
    const int path = blockIdx.x * 128 + w * 16 + (l & 15);
    const bool owner = (l < 16);
    float y = y0[0], Yv = Y0[0], t = 0.f, loss = 0.f;
    const float* dWp = dW + path * 3;
    const float* dZp = dZ + path * 3;

    #pragma unroll 1
    for (int i = 0; i < NSTEPS; ++i) {
        float dw0 = 0.f, dw1 = 0.f, dw2 = 0.f, dz0 = 0.f, dz1 = 0.f, dz2 = 0.f;
        if (owner) {
            dw0 = dWp[0] * SQDT; dw1 = dWp[1] * SQDT; dw2 = dWp[2] * SQDT;
            dz0 = dZp[0] * SQDT; dz1 = dZp[1] * SQDT; dz2 = dZp[2] * SQDT;
        }
        dWp += NB * 3; dZp += NB * 3;

        // y for the 2 rows this lane covers in the 16-row tile
        float yg  = __shfl_sync(0xffffffffu, y, g, 32);
        float yg8 = __shfl_sync(0xffffffffu, y, g + 8, 32);

        float zo0 = 0.f, zo1 = 0.f, zo2 = 0.f, qvv = 0.f;

        #pragma unroll
        for (int m = 0; m < 2; ++m) {
            // ---- layer 1 in m16n8k16 A-fragment layout (single fp16) ----
            // A[kt][e][s]: e=0 -> cols 16kt+2tq(+1), e=1 -> +8; s=0 row g, s=1 row g+8
            u32 A[4][2][2];
            #pragma unroll
            for (int kt = 0; kt < 4; ++kt) {
                #pragma unroll
                for (int e = 0; e < 2; ++e) {
                    int c0 = 16 * kt + 2 * tq + 8 * e;
                    float4 p0 = W1P[m][c0];
                    float4 p1 = W1P[m][c0 + 1];
                    float al0 = fmaf(t, p0.x, p0.z);
                    float al1 = fmaf(t, p1.x, p1.z);
                    float hg0 = fmaxf(fmaf(yg,  p0.y, al0), 0.f);
                    float hg1 = fmaxf(fmaf(yg,  p1.y, al1), 0.f);
                    float h80 = fmaxf(fmaf(yg8, p0.y, al0), 0.f);
                    float h81 = fmaxf(fmaf(yg8, p1.y, al1), 0.f);
                    A[kt][e][0] = h2u(__floats2half2_rn(hg0, hg1));
                    A[kt][e][1] = h2u(__floats2half2_rn(h80, h81));
                }
            }

            // ---- GEMM: kt-outer, 8 persistent nt accumulators, 1 MMA/pos ----
            float dacc[8][4];
            #pragma unroll
            for (int nt = 0; nt < 8; ++nt)
                #pragma unroll
                for (int j = 0; j < 4; ++j) dacc[nt][j] = 0.f;

            #pragma unroll
            for (int kt = 0; kt < 4; ++kt) {
                #pragma unroll
                for (int nt = 0; nt < 8; ++nt) {
                    mma16816(dacc[nt],
                             A[kt][0][0], A[kt][0][1], A[kt][1][0], A[kt][1][1],
                             Bl[m][kt][nt], Bh[m][kt][nt]);
                }
            }

            // ---- fused epilogue: relu(+b2 in w3.w) then layer-3 per-row sums ----
            // D mapping: d[0]=D[g][n0], d[1]=D[g][n0+1], d[2]=D[g+8][n0], d[3]=D[g+8][n0+1]
            float og[3]  = {0.f, 0.f, 0.f};
            float og8[3] = {0.f, 0.f, 0.f};
            #pragma unroll
            for (int nt = 0; nt < 8; ++nt) {
                int n0 = 8 * nt + 2 * tq;
                float4 w30 = W3P[m][n0];
                float4 w31 = W3P[m][n0 + 1];
                const float* d = dacc[nt];
                float h0 = fmaxf(d[0] + w30.w, 0.f);
                float h1 = fmaxf(d[1] + w31.w, 0.f);
                og[0] = fmaf(h0, w30.x, fmaf(h1, w31.x, og[0]));
                og[1] = fmaf(h0, w30.y, fmaf(h1, w31.y, og[1]));
                og[2] = fmaf(h0, w30.z, fmaf(h1, w31.z, og[2]));
                float h2v = fmaxf(d[2] + w30.w, 0.f);
                float h3 = fmaxf(d[3] + w31.w, 0.f);
                og8[0] = fmaf(h2v, w30.x, fmaf(h3, w31.x, og8[0]));
                og8[1] = fmaf(h2v, w30.y, fmaf(h3, w31.y, og8[1]));
                og8[2] = fmaf(h2v, w30.z, fmaf(h3, w31.z, og8[2]));
            }

            // quad reduction over tq (cols), then redistribute rows -> path lanes
            const int srcl = (l & 7) * 4;
            #pragma unroll
            for (int j = 0; j < 3; ++j) {
                if (m == 1 && j > 0) break;   // q-MLP only has output 0
                float v = og[j];
                v += __shfl_xor_sync(0xffffffffu, v, 1, 32);
                v += __shfl_xor_sync(0xffffffffu, v, 2, 32);
                float v8 = og8[j];
                v8 += __shfl_xor_sync(0xffffffffu, v8, 1, 32);
                v8 += __shfl_xor_sync(0xffffffffu, v8, 2, 32);
                // lane p wants row p: p<8 -> v at lane 4p ; p>=8 -> v8 at lane 4(p-8)
                float a = __shfl_sync(0xffffffffu, v, srcl, 32);
                float b = __shfl_sync(0xffffffffu, v8, srcl, 32);
                float val = (l & 8) ? b : a;
                if (m == 0) {
                    if (j == 0) zo0 = val + B3S[0][0];
                    else if (j == 1) zo1 = val + B3S[0][1];
                    else zo2 = val + B3S[0][2];
                } else {
                    qvv = val + B3S[1][0];
                }
            }
        }

        // ---- SDE / BSDE update (residual = z.dw - z.dz; Y cancels) ----
        if (owner) {
            float zdw = zo0 * dw0 + zo1 * dw1 + zo2 * dw2;
            float zdz = zo0 * dz0 + zo1 * dz1 + zo2 * dz2;
            float f = 0.5f * qvv * qvv;
            y  = y + qvv * DTC + SIG0 * (dw0 + dw1 + dw2);
            Yv = Yv - f * DTC + zdw;
            float r = zdw - zdz;
            loss = fmaf(r, r, loss);
        }
        t += DTC;
    }
    if (owner) {
        float term = Yv - y * y;
        loss = fmaf(term, term, loss);
    } else {
        loss = 0.f;
    }

    // ---------------- reduction ----------------
    red[tx] = loss;
    __syncthreads();
    #pragma unroll
    for (int s = 128; s > 0; s >>= 1) {
        if (tx < s) red[tx] += red[tx + s];
        __syncthreads();
    }
    if (tx == 0) {
        g_partials[blockIdx.x] = red[0];
        __threadfence();
        unsigned int prev = atomicAdd(&g_count, 1u);
        is_last = (prev == gridDim.x - 1) ? 1 : 0;
    }
    __syncthreads();
    if (is_last) {
        __threadfence();
        red[tx] = (tx < 128) ? g_partials[tx] : 0.f;
        __syncthreads();
        #pragma unroll
        for (int s = 128; s > 0; s >>= 1) {
            if (tx < s) red[tx] += red[tx + s];
            __syncthreads();
        }
        if (tx == 0) {
            out[0] = red[0] * (1.0f / (float)NB);
            g_count = 0;               // reset for graph replay
        }
    }
}

extern "C" void kernel_launch(void* const* d_in, const int* in_sizes, int n_in,
                              void* d_out, int out_size)
{
    const float* y0  = (const float*)d_in[0];
    const float* Y0  = (const float*)d_in[1];
    const float* zW1 = (const float*)d_in[2];
    const float* zb1 = (const float*)d_in[3];
    const float* zW2 = (const float*)d_in[4];
    const float* zb2 = (const float*)d_in[5];
    const float* zW3 = (const float*)d_in[6];
    const float* zb3 = (const float*)d_in[7];
    const float* qW1 = (const float*)d_in[8];
    const float* qb1 = (const float*)d_in[9];
    const float* qW2 = (const float*)d_in[10];
    const float* qb2 = (const float*)d_in[11];
    const float* qW3 = (const float*)d_in[12];
    const float* qb3 = (const float*)d_in[13];
    const float* dW  = (const float*)d_in[14];
    const float* dZ  = (const float*)d_in[15];

    bsde_mma<<<128, 256>>>(y0, Y0, zW1, zb1, zW2, zb2, zW3, zb3,
                           qW1, qb1, qW2, qb2, qW3, qb3, dW, dZ,
                           (float*)d_out);
}

// round 13
// speedup vs baseline: 2.8473x; 1.1811x over previous
#include <cuda_runtime.h>
#include <cuda_fp16.h>

#define NB 16384
#define NSTEPS 100
#define DTC 0.01f
#define SQDT 0.1f
#define SIG0 0.5f

typedef unsigned int u32;
typedef unsigned long long u64;

__device__ __forceinline__ u32 h2u(__half2 h) {
    u32 r; *(__half2*)&r = h; return r;
}
__device__ __forceinline__ __half2 u2h(u32 u) {
    __half2 h; *(u32*)&h = u; return h;
}

__device__ __forceinline__ void mma16816(float* d, const u32 a0, const u32 a1,
                                         const u32 a2, const u32 a3,
                                         const u32 b0, const u32 b1) {
    asm volatile(
        "mma.sync.aligned.m16n8k16.row.col.f32.f16.f16.f32 "
        "{%0,%1,%2,%3}, {%4,%5,%6,%7}, {%8,%9}, {%0,%1,%2,%3};"
        : "+f"(d[0]), "+f"(d[1]), "+f"(d[2]), "+f"(d[3])
        : "r"(a0), "r"(a1), "r"(a2), "r"(a3), "r"(b0), "r"(b1));
}
__device__ __forceinline__ void mma16808(float* d, const u32 a0, const u32 a1,
                                         const u32 b0) {
    asm volatile(
        "mma.sync.aligned.m16n8k8.row.col.f32.f16.f16.f32 "
        "{%0,%1,%2,%3}, {%4,%5}, {%6}, {%0,%1,%2,%3};"
        : "+f"(d[0]), "+f"(d[1]), "+f"(d[2]), "+f"(d[3])
        : "r"(a0), "r"(a1), "r"(b0));
}

// relu(cvt(f0,f1)) as packed half2
__device__ __forceinline__ u32 relu_pack(float f0, float f1) {
    __half2 h = __floats2half2_rn(f0, f1);
    __half2 z = __floats2half2_rn(0.f, 0.f);
    return h2u(__hmax2(h, z));
}

__device__ float g_partials[128];
__device__ unsigned int g_count = 0;

__global__ __launch_bounds__(256) void bsde_mma(
    const float* __restrict__ y0, const float* __restrict__ Y0,
    const float* __restrict__ zW1, const float* __restrict__ zb1,
    const float* __restrict__ zW2, const float* __restrict__ zb2,
    const float* __restrict__ zW3, const float* __restrict__ zb3,
    const float* __restrict__ qW1, const float* __restrict__ qb1,
    const float* __restrict__ qW2, const float* __restrict__ qb2,
    const float* __restrict__ qW3, const float* __restrict__ qb3,
    const float* __restrict__ dW, const float* __restrict__ dZ,
    float* __restrict__ out)
{
    // W2 staging (read once into regs): pos = n*16 + kt*4 + tq
    __shared__ u64 W2S[2][1024];
    // layer-3 B-fragments: [m][kt3][tq][g], u64 = (b0, b1)
    __shared__ u64 W3BS[2][4][4][8];
    // b2 as half2: [m][nt][tq] = (b2[8nt+2tq], b2[8nt+2tq+1])
    __shared__ u32 B2H[2][8][4];
    __shared__ float B3S[2][4];
    __shared__ float red[256];
    __shared__ int   is_last;

    const int tx = threadIdx.x;
    const int l  = tx & 31;
    const int w  = tx >> 5;          // 8 warps, each owns 16 paths
    const int g  = l >> 2;
    const int tq = l & 3;

    // ---------------- stage W2 ----------------
    for (int idx = tx; idx < 4096; idx += 256) {
        int k = idx >> 6, n = idx & 63;
        int kt = k >> 4, r = k & 15;
        int tt, slot;
        if (r < 8) { tt = r >> 1; slot = r & 1; }
        else       { tt = (r - 8) >> 1; slot = 2 + (r & 1); }
        int pos = n * 16 + kt * 4 + tt;
        ((__half*)&W2S[0][pos])[slot] = __float2half_rn(zW2[idx]);
        ((__half*)&W2S[1][pos])[slot] = __float2half_rn(qW2[idx]);
    }
    // ---------------- stage W3 B-fragments (zero-padded to 8 cols) ----------------
    if (tx < 256) {
        int idx = tx;
        int g5 = idx & 7, tq5 = (idx >> 3) & 3, kt5 = (idx >> 5) & 3, m5 = idx >> 7;
        int k0 = 16 * kt5 + 2 * tq5;
        float w00, w01, w10, w11;
        if (m5 == 0) {
            w00 = (g5 < 3) ? zW3[k0 * 3 + g5] : 0.f;
            w01 = (g5 < 3) ? zW3[(k0 + 1) * 3 + g5] : 0.f;
            w10 = (g5 < 3) ? zW3[(k0 + 8) * 3 + g5] : 0.f;
            w11 = (g5 < 3) ? zW3[(k0 + 9) * 3 + g5] : 0.f;
        } else {
            w00 = (g5 == 0) ? qW3[k0] : 0.f;
            w01 = (g5 == 0) ? qW3[k0 + 1] : 0.f;
            w10 = (g5 == 0) ? qW3[k0 + 8] : 0.f;
            w11 = (g5 == 0) ? qW3[k0 + 9] : 0.f;
        }
        u64 v = (u64)h2u(__floats2half2_rn(w00, w01))
              | ((u64)h2u(__floats2half2_rn(w10, w11)) << 32);
        W3BS[m5][kt5][tq5][g5] = v;
    }
    if (tx < 64) {
        int idx = tx;
        int tq6 = idx & 3, nt6 = (idx >> 2) & 7, m6 = idx >> 5;
        const float* b2 = m6 ? qb2 : zb2;
        int n = 8 * nt6 + 2 * tq6;
        B2H[m6][nt6][tq6] = h2u(__floats2half2_rn(b2[n], b2[n + 1]));
    }
    if (tx < 4) {
        B3S[0][tx] = (tx < 3) ? zb3[tx] : 0.f;
        B3S[1][tx] = (tx == 0) ? qb3[0] : 0.f;
    }
    __syncthreads();

    // ---------------- hoist layer-2 B fragments (once) ----------------
    u32 Bl[2][4][8], Bh[2][4][8];
    #pragma unroll
    for (int m = 0; m < 2; ++m)
        #pragma unroll
        for (int kt = 0; kt < 4; ++kt)
            #pragma unroll
            for (int nt = 0; nt < 8; ++nt) {
                u64 b = W2S[m][(8 * nt + g) * 16 + kt * 4 + tq];
                Bl[m][kt][nt] = (u32)b;
                Bh[m][kt][nt] = (u32)(b >> 32);
            }

    // ---------------- hoist layer-1 B fragments (K=8: rows t,y,1,0..) ----------------
    // B[0][n]=W1t[n], B[1][n]=W1y[n], B[2][n]=b1[n], rest 0.
    // b-frag = (B[2tq][n], B[2tq+1][n]),  n = 8*nt1 + g
    u32 W1Bf[2][8];
    #pragma unroll
    for (int m = 0; m < 2; ++m) {
        const float* W1 = m ? qW1 : zW1;
        const float* b1 = m ? qb1 : zb1;
        #pragma unroll
        for (int nt1 = 0; nt1 < 8; ++nt1) {
            int n = 8 * nt1 + g;
            u32 v = 0;
            if (tq == 0)      v = h2u(__floats2half2_rn(W1[n], W1[64 + n]));
            else if (tq == 1) v = h2u(__floats2half2_rn(b1[n], 0.f));
            W1Bf[m][nt1] = v;
        }
    }

    // ---------------- per-path state: lane l < 16 owns path base + l ----------------
    const int path = blockIdx.x * 128 + w * 16 + (l & 15);
    const bool owner = (l < 16);
    float y = y0[0], Yv = Y0[0], t = 0.f, loss = 0.f;
    const float* dWp = dW + path * 3;
    const float* dZp = dZ + path * 3;

    #pragma unroll 1
    for (int i = 0; i < NSTEPS; ++i) {
        float dw0 = 0.f, dw1 = 0.f, dw2 = 0.f, dz0 = 0.f, dz1 = 0.f, dz2 = 0.f;
        if (owner) {
            dw0 = dWp[0] * SQDT; dw1 = dWp[1] * SQDT; dw2 = dWp[2] * SQDT;
            dz0 = dZp[0] * SQDT; dz1 = dZp[1] * SQDT; dz2 = dZp[2] * SQDT;
        }
        dWp += NB * 3; dZp += NB * 3;

        // y for rows g, g+8 of this warp's 16-path tile
        float yg  = __shfl_sync(0xffffffffu, y, g, 32);
        float yg8 = __shfl_sync(0xffffffffu, y, g + 8, 32);

        // layer-1 A fragment: A[p][k] = (t, y_p, 1, 0...) -- same for both MLPs
        u32 a1_0, a1_1;
        if (tq == 0) {
            a1_0 = h2u(__floats2half2_rn(t, yg));
            a1_1 = h2u(__floats2half2_rn(t, yg8));
        } else if (tq == 1) {
            a1_0 = 0x00003C00u;   // half2(1.0, 0.0)
            a1_1 = 0x00003C00u;
        } else {
            a1_0 = 0u;
            a1_1 = 0u;
        }

        float zd0 = 0.f, zd1 = 0.f, zd2 = 0.f, zd3 = 0.f, qd0 = 0.f, qd2 = 0.f;

        #pragma unroll
        for (int m = 0; m < 2; ++m) {
            // ---- layer 1 MMA (m16n8k8), bias folded via "1" column ----
            float D1[8][4];
            #pragma unroll
            for (int nt1 = 0; nt1 < 8; ++nt1)
                #pragma unroll
                for (int j = 0; j < 4; ++j) D1[nt1][j] = 0.f;
            #pragma unroll
            for (int nt1 = 0; nt1 < 8; ++nt1)
                mma16808(D1[nt1], a1_0, a1_1, W1Bf[m][nt1]);

            // relu + pack -> layer-2 A fragments
            u32 A2[4][4];
            #pragma unroll
            for (int kt = 0; kt < 4; ++kt) {
                A2[kt][0] = relu_pack(D1[2 * kt][0],     D1[2 * kt][1]);
                A2[kt][1] = relu_pack(D1[2 * kt][2],     D1[2 * kt][3]);
                A2[kt][2] = relu_pack(D1[2 * kt + 1][0], D1[2 * kt + 1][1]);
                A2[kt][3] = relu_pack(D1[2 * kt + 1][2], D1[2 * kt + 1][3]);
            }

            // ---- layer 2 MMA (m16n8k16), kt-outer, persistent accumulators ----
            float dacc[8][4];
            #pragma unroll
            for (int nt = 0; nt < 8; ++nt)
                #pragma unroll
                for (int j = 0; j < 4; ++j) dacc[nt][j] = 0.f;
            #pragma unroll
            for (int kt = 0; kt < 4; ++kt)
                #pragma unroll
                for (int nt = 0; nt < 8; ++nt)
                    mma16816(dacc[nt],
                             A2[kt][0], A2[kt][1], A2[kt][2], A2[kt][3],
                             Bl[m][kt][nt], Bh[m][kt][nt]);

            // ---- +b2, relu, pack -> layer-3 A fragments ----
            u32 A3[4][4];
            #pragma unroll
            for (int kt3 = 0; kt3 < 4; ++kt3) {
                __half2 b2a = u2h(B2H[m][2 * kt3][tq]);
                __half2 b2b = u2h(B2H[m][2 * kt3 + 1][tq]);
                __half2 z2 = __floats2half2_rn(0.f, 0.f);
                __half2 v;
                v = __hadd2(__floats2half2_rn(dacc[2 * kt3][0], dacc[2 * kt3][1]), b2a);
                A3[kt3][0] = h2u(__hmax2(v, z2));
                v = __hadd2(__floats2half2_rn(dacc[2 * kt3][2], dacc[2 * kt3][3]), b2a);
                A3[kt3][1] = h2u(__hmax2(v, z2));
                v = __hadd2(__floats2half2_rn(dacc[2 * kt3 + 1][0], dacc[2 * kt3 + 1][1]), b2b);
                A3[kt3][2] = h2u(__hmax2(v, z2));
                v = __hadd2(__floats2half2_rn(dacc[2 * kt3 + 1][2], dacc[2 * kt3 + 1][3]), b2b);
                A3[kt3][3] = h2u(__hmax2(v, z2));
            }

            // ---- layer 3 MMA (m16n8k16, K=64) ----
            float D3[4] = {0.f, 0.f, 0.f, 0.f};
            #pragma unroll
            for (int kt3 = 0; kt3 < 4; ++kt3) {
                u64 w3 = W3BS[m][kt3][tq][g];
                mma16816(D3, A3[kt3][0], A3[kt3][1], A3[kt3][2], A3[kt3][3],
                         (u32)w3, (u32)(w3 >> 32));
            }
            if (m == 0) { zd0 = D3[0]; zd1 = D3[1]; zd2 = D3[2]; zd3 = D3[3]; }
            else        { qd0 = D3[0]; qd2 = D3[2]; }
        }

        // ---- redistribute: path p reads D3[p][col] ----
        // D3 frag: d0=(g,2tq) d1=(g,2tq+1) d2=(g+8,2tq) d3=(g+8,2tq+1)
        const int srcA = 4 * (l & 7);
        const bool hi8 = (l & 8) != 0;
        float va, vb;
        va = __shfl_sync(0xffffffffu, zd0, srcA, 32);
        vb = __shfl_sync(0xffffffffu, zd2, srcA, 32);
        float zo0 = (hi8 ? vb : va) + B3S[0][0];
        va = __shfl_sync(0xffffffffu, zd1, srcA, 32);
        vb = __shfl_sync(0xffffffffu, zd3, srcA, 32);
        float zo1 = (hi8 ? vb : va) + B3S[0][1];
        va = __shfl_sync(0xffffffffu, zd0, srcA + 1, 32);
        vb = __shfl_sync(0xffffffffu, zd2, srcA + 1, 32);
        float zo2 = (hi8 ? vb : va) + B3S[0][2];
        va = __shfl_sync(0xffffffffu, qd0, srcA, 32);
        vb = __shfl_sync(0xffffffffu, qd2, srcA, 32);
        float qvv = (hi8 ? vb : va) + B3S[1][0];

        // ---- SDE / BSDE update (residual = z.dw - z.dz; Y cancels) ----
        if (owner) {
            float zdw = zo0 * dw0 + zo1 * dw1 + zo2 * dw2;
            float zdz = zo0 * dz0 + zo1 * dz1 + zo2 * dz2;
            float f = 0.5f * qvv * qvv;
            y  = y + qvv * DTC + SIG0 * (dw0 + dw1 + dw2);
            Yv = Yv - f * DTC + zdw;
            float r = zdw - zdz;
            loss = fmaf(r, r, loss);
        }
        t += DTC;
    }
    if (owner) {
        float term = Yv - y * y;
        loss = fmaf(term, term, loss);
    } else {
        loss = 0.f;
    }

    // ---------------- reduction ----------------
    red[tx] = loss;
    __syncthreads();
    #pragma unroll
    for (int s = 128; s > 0; s >>= 1) {
        if (tx < s) red[tx] += red[tx + s];
        __syncthreads();
    }
    if (tx == 0) {
        g_partials[blockIdx.x] = red[0];
        __threadfence();
        unsigned int prev = atomicAdd(&g_count, 1u);
        is_last = (prev == gridDim.x - 1) ? 1 : 0;
    }
    __syncthreads();
    if (is_last) {
        __threadfence();
        red[tx] = (tx < 128) ? g_partials[tx] : 0.f;
        __syncthreads();
        #pragma unroll
        for (int s = 128; s > 0; s >>= 1) {
            if (tx < s) red[tx] += red[tx + s];
            __syncthreads();
        }
        if (tx == 0) {
            out[0] = red[0] * (1.0f / (float)NB);
            g_count = 0;               // reset for graph replay
        }
    }
}

extern "C" void kernel_launch(void* const* d_in, const int* in_sizes, int n_in,
                              void* d_out, int out_size)
{
    const float* y0  = (const float*)d_in[0];
    const float* Y0  = (const float*)d_in[1];
    const float* zW1 = (const float*)d_in[2];
    const float* zb1 = (const float*)d_in[3];
    const float* zW2 = (const float*)d_in[4];
    const float* zb2 = (const float*)d_in[5];
    const float* zW3 = (const float*)d_in[6];
    const float* zb3 = (const float*)d_in[7];
    const float* qW1 = (const float*)d_in[8];
    const float* qb1 = (const float*)d_in[9];
    const float* qW2 = (const float*)d_in[10];
    const float* qb2 = (const float*)d_in[11];
    const float* qW3 = (const float*)d_in[12];
    const float* qb3 = (const float*)d_in[13];
    const float* dW  = (const float*)d_in[14];
    const float* dZ  = (const float*)d_in[15];

    bsde_mma<<<128, 256>>>(y0, Y0, zW1, zb1, zW2, zb2, zW3, zb3,
                           qW1, qb1, qW2, qb2, qW3, qb3, dW, dZ,
                           (float*)d_out);
}